// round 8
// baseline (speedup 1.0000x reference)
#include <cuda_runtime.h>
#include <cuda_fp16.h>
#include <cstdint>

#define D 128
#define NMAX 50000
#define EMAX 800000
#define D4 (D/4)    // 32 float4 per fp32 row
#define DH2 (D/4)   // 32 uint2 (4 halves each) per fp16 row

// ---------------- scratch (no allocations allowed) ----------------
__device__ int    g_deg[NMAX];
__device__ float  g_dinv[NMAX];
__device__ int    g_rowstart[NMAX];
__device__ int    g_cur[NMAX];
__device__ int    g_esrc[EMAX];
__device__ __half g_h[(size_t)NMAX * D];   // message buffer (fp16, dinv-scaled)
__device__ float  g_a[(size_t)NMAX * D];   // layer-1 activation (fp32)
__device__ int    g_is64;

__device__ __forceinline__ int load_idx(const int* __restrict__ ei, size_t pos) {
    return g_is64 ? ei[2 * pos] : ei[pos];
}

__device__ __forceinline__ unsigned pack_h2(float a, float b) {
    __half2 h = __floats2half2_rn(a, b);
    return *reinterpret_cast<unsigned*>(&h);
}

// ---------------- init degrees + dtype detect ----------------
__global__ void k_init(const int* __restrict__ ei, int n) {
    int i = blockIdx.x * blockDim.x + threadIdx.x;
    if (i < n) g_deg[i] = 1;
    if (blockIdx.x == 0 && threadIdx.x == 0) {
        int all0 = 1;
        for (int j = 0; j < 64; ++j)
            if (ei[2 * j + 1] != 0) { all0 = 0; break; }
        g_is64 = all0;
    }
}

// ---------------- GEMM body: fp32 A,W -> fp16 C ----------------
#define FMA4(acc, s, b) { acc.x = fmaf(s, b.x, acc.x); acc.y = fmaf(s, b.y, acc.y); \
                          acc.z = fmaf(s, b.z, acc.z); acc.w = fmaf(s, b.w, acc.w); }

template<bool SCALE_OUT>
__device__ __forceinline__ void gemm_body(int bid, int tid,
                                          const float* __restrict__ A,
                                          const float* __restrict__ Wm,
                                          __half* __restrict__ C, int M) {
    int lane = tid & 31;
    int rs   = tid >> 5;
    int row0 = bid * 32 + rs * 4;
    if (row0 >= M) return;

    const float4* A4 = (const float4*)A;
    const float4* W4 = (const float4*)Wm;

    float4 acc0 = make_float4(0,0,0,0), acc1 = acc0, acc2 = acc0, acc3 = acc0;

    size_t ar0 = (size_t)(row0 + 0) * D4;
    size_t ar1 = (size_t)(row0 + 1) * D4;
    size_t ar2 = (size_t)(row0 + 2) * D4;
    size_t ar3 = (size_t)(row0 + 3) * D4;

#pragma unroll 4
    for (int k4 = 0; k4 < D4; ++k4) {
        float4 a0 = A4[ar0 + k4];
        float4 a1 = A4[ar1 + k4];
        float4 a2 = A4[ar2 + k4];
        float4 a3 = A4[ar3 + k4];
        int k = k4 * 4;
        float4 b0 = W4[(size_t)(k + 0) * D4 + lane];
        float4 b1 = W4[(size_t)(k + 1) * D4 + lane];
        float4 b2 = W4[(size_t)(k + 2) * D4 + lane];
        float4 b3 = W4[(size_t)(k + 3) * D4 + lane];

        FMA4(acc0, a0.x, b0); FMA4(acc0, a0.y, b1); FMA4(acc0, a0.z, b2); FMA4(acc0, a0.w, b3);
        FMA4(acc1, a1.x, b0); FMA4(acc1, a1.y, b1); FMA4(acc1, a1.z, b2); FMA4(acc1, a1.w, b3);
        FMA4(acc2, a2.x, b0); FMA4(acc2, a2.y, b1); FMA4(acc2, a2.z, b2); FMA4(acc2, a2.w, b3);
        FMA4(acc3, a3.x, b0); FMA4(acc3, a3.y, b1); FMA4(acc3, a3.z, b2); FMA4(acc3, a3.w, b3);
    }

    if (SCALE_OUT) {
        float s0 = g_dinv[row0 + 0], s1 = g_dinv[row0 + 1];
        float s2 = g_dinv[row0 + 2], s3 = g_dinv[row0 + 3];
        acc0.x *= s0; acc0.y *= s0; acc0.z *= s0; acc0.w *= s0;
        acc1.x *= s1; acc1.y *= s1; acc1.z *= s1; acc1.w *= s1;
        acc2.x *= s2; acc2.y *= s2; acc2.z *= s2; acc2.w *= s2;
        acc3.x *= s3; acc3.y *= s3; acc3.z *= s3; acc3.w *= s3;
    }

    uint2* C2 = (uint2*)C;
    C2[(size_t)(row0 + 0) * DH2 + lane] = make_uint2(pack_h2(acc0.x, acc0.y), pack_h2(acc0.z, acc0.w));
    C2[(size_t)(row0 + 1) * DH2 + lane] = make_uint2(pack_h2(acc1.x, acc1.y), pack_h2(acc1.z, acc1.w));
    C2[(size_t)(row0 + 2) * DH2 + lane] = make_uint2(pack_h2(acc2.x, acc2.y), pack_h2(acc2.z, acc2.w));
    C2[(size_t)(row0 + 3) * DH2 + lane] = make_uint2(pack_h2(acc3.x, acc3.y), pack_h2(acc3.z, acc3.w));
}

// ---------------- mega: GEMM1 blocks + degree-count blocks ----------------
__global__ void k_mega(const float* __restrict__ A, const float* __restrict__ Wm,
                       __half* __restrict__ C, int M,
                       const int* __restrict__ ei, int E, int gemmBlocks) {
    if ((int)blockIdx.x < gemmBlocks) {
        gemm_body<false>(blockIdx.x, threadIdx.x, A, Wm, C, M);
    } else {
        int e = (blockIdx.x - gemmBlocks) * blockDim.x + threadIdx.x;
        if (e < E) atomicAdd(&g_deg[load_idx(ei, (size_t)E + e)], 1);
    }
}

__global__ void k_gemm2(const float* __restrict__ A, const float* __restrict__ Wm,
                        __half* __restrict__ C, int M) {
    gemm_body<true>(blockIdx.x, threadIdx.x, A, Wm, C, M);
}

// ---------------- scan: rowstart, cursors, dinv ----------------
__global__ void k_scan(int n) {
    __shared__ int part[1024];
    const int tid = threadIdx.x;
    const int chunk = (n + 1023) / 1024;
    const int beg = tid * chunk;
    const int end = min(beg + chunk, n);

    int s = 0;
    for (int i = beg; i < end; ++i) s += g_deg[i] - 1;
    part[tid] = s;
    __syncthreads();

    for (int off = 1; off < 1024; off <<= 1) {
        int v = (tid >= off) ? part[tid - off] : 0;
        __syncthreads();
        part[tid] += v;
        __syncthreads();
    }

    int run = (tid > 0) ? part[tid - 1] : 0;
    for (int i = beg; i < end; ++i) {
        int dg = g_deg[i];
        g_rowstart[i] = run;
        g_cur[i] = run;
        g_dinv[i] = rsqrtf((float)dg);
        run += dg - 1;
    }
}

// ---------------- scale h rows by dinv (h fp16, in place) ----------------
// thread per uint2 (4 halves). Coalesced: ~25.6MB traffic, ~4us.
__global__ void k_scaleh(__half* __restrict__ H, int n) {
    int idx = blockIdx.x * blockDim.x + threadIdx.x;
    int total = n * DH2;
    if (idx >= total) return;
    int node = idx >> 5;
    float di = g_dinv[node];
    uint2 raw = ((uint2*)H)[idx];
    __half2* ph = (__half2*)&raw;
    float2 lo = __half22float2(ph[0]);
    float2 hi = __half22float2(ph[1]);
    ((uint2*)H)[idx] = make_uint2(pack_h2(lo.x * di, lo.y * di),
                                  pack_h2(hi.x * di, hi.y * di));
}

// ---------------- CSR fill: src index only ----------------
__global__ void k_fill(const int* __restrict__ ei, int E) {
    int e = blockIdx.x * blockDim.x + threadIdx.x;
    if (e >= E) return;
    int s = load_idx(ei, (size_t)e);
    int d = load_idx(ei, (size_t)E + e);
    int pos = atomicAdd(&g_cur[d], 1);
    g_esrc[pos] = s;
}

// ---------------- pure gather-add aggregation + bias + ReLU ---------------
// H rows are pre-scaled by dinv[src]. One warp per dst node, lane = 4 cols.
// Software-pipelined: next batch of 8 indices prefetched during gathers.
__device__ __forceinline__ void add_h4(float4& acc, uint2 raw) {
    __half2* ph = (__half2*)&raw;
    float2 lo = __half22float2(ph[0]);
    float2 hi = __half22float2(ph[1]);
    acc.x += lo.x; acc.y += lo.y; acc.z += hi.x; acc.w += hi.y;
}

__global__ void k_agg(const __half* __restrict__ H,
                      const float* __restrict__ b,
                      float* __restrict__ out, int n) {
    int warp = (int)((blockIdx.x * (size_t)blockDim.x + threadIdx.x) >> 5);
    int lane = threadIdx.x & 31;
    if (warp >= n) return;
    int node = warp;

    const uint2* H2 = (const uint2*)H;
    float di = g_dinv[node];

    float4 acc = make_float4(0, 0, 0, 0);
    add_h4(acc, H2[(size_t)node * DH2 + lane]);   // self-loop (pre-scaled)

    int p   = g_rowstart[node];
    int end = p + (g_deg[node] - 1);

    int c0, c1, c2, c3, c4, c5, c6, c7;
    bool have = (p + 8 <= end);
    if (have) {
        c0 = g_esrc[p+0]; c1 = g_esrc[p+1]; c2 = g_esrc[p+2]; c3 = g_esrc[p+3];
        c4 = g_esrc[p+4]; c5 = g_esrc[p+5]; c6 = g_esrc[p+6]; c7 = g_esrc[p+7];
    }
    while (have) {
        bool nxt = (p + 16 <= end);
        int n0, n1, n2, n3, n4, n5, n6, n7;
        if (nxt) {   // prefetch next indices while gathers are in flight
            n0 = g_esrc[p+8];  n1 = g_esrc[p+9];  n2 = g_esrc[p+10]; n3 = g_esrc[p+11];
            n4 = g_esrc[p+12]; n5 = g_esrc[p+13]; n6 = g_esrc[p+14]; n7 = g_esrc[p+15];
        }
        uint2 v0 = H2[(size_t)c0 * DH2 + lane];
        uint2 v1 = H2[(size_t)c1 * DH2 + lane];
        uint2 v2 = H2[(size_t)c2 * DH2 + lane];
        uint2 v3 = H2[(size_t)c3 * DH2 + lane];
        uint2 v4 = H2[(size_t)c4 * DH2 + lane];
        uint2 v5 = H2[(size_t)c5 * DH2 + lane];
        uint2 v6 = H2[(size_t)c6 * DH2 + lane];
        uint2 v7 = H2[(size_t)c7 * DH2 + lane];
        add_h4(acc, v0); add_h4(acc, v1); add_h4(acc, v2); add_h4(acc, v3);
        add_h4(acc, v4); add_h4(acc, v5); add_h4(acc, v6); add_h4(acc, v7);
        p += 8;
        if (nxt) { c0=n0; c1=n1; c2=n2; c3=n3; c4=n4; c5=n5; c6=n6; c7=n7; }
        have = nxt;
    }
    // tail (<8 edges)
    for (; p + 3 < end; p += 4) {
        int s0 = g_esrc[p],   s1 = g_esrc[p+1];
        int s2 = g_esrc[p+2], s3 = g_esrc[p+3];
        uint2 v0 = H2[(size_t)s0 * DH2 + lane];
        uint2 v1 = H2[(size_t)s1 * DH2 + lane];
        uint2 v2 = H2[(size_t)s2 * DH2 + lane];
        uint2 v3 = H2[(size_t)s3 * DH2 + lane];
        add_h4(acc, v0); add_h4(acc, v1); add_h4(acc, v2); add_h4(acc, v3);
    }
    for (; p < end; ++p) {
        uint2 v0 = H2[(size_t)g_esrc[p] * DH2 + lane];
        add_h4(acc, v0);
    }

    float4 bv = ((const float4*)b)[lane];
    float4 r;
    r.x = fmaxf(fmaf(di, acc.x, bv.x), 0.f);
    r.y = fmaxf(fmaf(di, acc.y, bv.y), 0.f);
    r.z = fmaxf(fmaf(di, acc.z, bv.z), 0.f);
    r.w = fmaxf(fmaf(di, acc.w, bv.w), 0.f);
    ((float4*)out)[(size_t)node * D4 + lane] = r;
}

// ---------------- launch ----------------
extern "C" void kernel_launch(void* const* d_in, const int* in_sizes, int n_in,
                              void* d_out, int out_size) {
    const float* x  = (const float*)d_in[0];
    const int*   ei = (const int*)d_in[1];
    const float* W1 = (const float*)d_in[2];
    const float* b1 = (const float*)d_in[3];
    const float* W2 = (const float*)d_in[4];
    const float* b2 = (const float*)d_in[5];
    float* out = (float*)d_out;

    int n = in_sizes[0] / D;        // 50000
    int E = in_sizes[1] / 2;        // 800000

    __half* h;
    float*  a;
    cudaGetSymbolAddress((void**)&h, g_h);
    cudaGetSymbolAddress((void**)&a, g_a);

    int gemmBlocks  = (n + 31) / 32;
    int countBlocks = (E + 255) / 256;
    int aggBlocks   = (n * 32 + 255) / 256;   // 1 warp per node
    int sclBlocks   = (n * DH2 + 255) / 256;

    k_init<<<(n + 255) / 256, 256>>>(ei, n);
    // GEMM1 (unscaled h) overlapped with degree count
    k_mega<<<gemmBlocks + countBlocks, 256>>>(x, W1, h, n, ei, E, gemmBlocks);
    k_scan<<<1, 1024>>>(n);
    // pre-scale h rows by dinv -> layer-1 agg becomes pure gather-add
    k_scaleh<<<sclBlocks, 256>>>(h, n);
    k_fill<<<countBlocks, 256>>>(ei, E);

    // ---- layer 1 ----
    k_agg<<<aggBlocks, 256>>>(h, b1, a, n);

    // ---- layer 2: gemm epilogue scales by dinv -> pure gather-add ----
    k_gemm2<<<gemmBlocks, 256>>>(a, W2, h, n);
    k_agg<<<aggBlocks, 256>>>(h, b2, out, n);
}

// round 10
// speedup vs baseline: 1.2342x; 1.2342x over previous
#include <cuda_runtime.h>
#include <cuda_fp16.h>
#include <cuda_bf16.h>
#include <cstdint>

#define D 128
#define NMAX 50000
#define EMAX 800000
#define D4 (D/4)    // 32 float4 per fp32 row
#define DH2 (D/4)   // 32 uint2 per fp16 row

// ---------------- scratch (no allocations allowed) ----------------
__device__ int    g_deg[NMAX];
__device__ float  g_dinv[NMAX];
__device__ int    g_rowstart[NMAX];
__device__ int    g_cur[NMAX];
__device__ int    g_esrc[EMAX];
__device__ __half g_h[(size_t)NMAX * D];   // message buffer (fp16)
__device__ float  g_a[(size_t)NMAX * D];   // layer-1 activation (fp32)
__device__ int    g_is64;
// W split into bf16 hi/lo, TRANSPOSED: buf[n*128 + k] = bf16(W[k][n])
__device__ __align__(16) __nv_bfloat16 g_wh1[16384];
__device__ __align__(16) __nv_bfloat16 g_wl1[16384];
__device__ __align__(16) __nv_bfloat16 g_wh2[16384];
__device__ __align__(16) __nv_bfloat16 g_wl2[16384];

__device__ __forceinline__ int load_idx(const int* __restrict__ ei, size_t pos) {
    return g_is64 ? ei[2 * pos] : ei[pos];
}

__device__ __forceinline__ unsigned pack_bf2(__nv_bfloat16 lo, __nv_bfloat16 hi) {
    return ((unsigned)__bfloat16_as_ushort(hi) << 16) | __bfloat16_as_ushort(lo);
}

// ---------------- init degrees + dtype detect ----------------
__global__ void k_init(const int* __restrict__ ei, int n) {
    int i = blockIdx.x * blockDim.x + threadIdx.x;
    if (i < n) g_deg[i] = 1;
    if (blockIdx.x == 0 && threadIdx.x == 0) {
        int all0 = 1;
        for (int j = 0; j < 64; ++j)
            if (ei[2 * j + 1] != 0) { all0 = 0; break; }
        g_is64 = all0;
    }
}

// ---------------- prep: W -> bf16 hi/lo transposed  +  degree count -------
__global__ void k_pre(const float* __restrict__ W1, const float* __restrict__ W2,
                      const int* __restrict__ ei, int E) {
    if (blockIdx.x < 128) {
        int mat = blockIdx.x >> 6;
        int idx = (blockIdx.x & 63) * 256 + threadIdx.x;
        if (idx < 16384) {
            const float* W = mat ? W2 : W1;
            __nv_bfloat16* WH = mat ? g_wh2 : g_wh1;
            __nv_bfloat16* WL = mat ? g_wl2 : g_wl1;
            int k = idx >> 7, j = idx & 127;
            float w = W[idx];                       // W[k][j]
            __nv_bfloat16 h = __float2bfloat16_rn(w);
            __nv_bfloat16 l = __float2bfloat16_rn(w - __bfloat162float(h));
            WH[j * 128 + k] = h;                    // transposed [n][k]
            WL[j * 128 + k] = l;
        }
    } else {
        int e = (blockIdx.x - 128) * blockDim.x + threadIdx.x;
        if (e < E) atomicAdd(&g_deg[load_idx(ei, (size_t)E + e)], 1);
    }
}

// ---------------- HMMA GEMM: C_fp16[M,128] = A_fp32[M,128] @ W ------------
// mma.sync m16n8k16 bf16 (sm_80+ base-target instruction, works on compute_103).
// Split-bf16: acc += Ah*Wh + Al*Wh + Ah*Wl (fp32 accum).
// Block = 64 rows x 128 cols, 8 warps (4 m x 2 n), warp = 16x64.
// smem rows padded to 136 bf16 (68 uints) -> all fragment LDS conflict-free.
#define AS 68                      // uint stride per smem row
#define SM_AH 0
#define SM_AL 4352                 // 64*68
#define SM_BH 8704
#define SM_BL 17408                // 8704 + 128*68
#define SM_UINTS 26112
#define SM_BYTES (SM_UINTS * 4)

__device__ __forceinline__ void mma_bf16(float4& d,
                                         unsigned a0, unsigned a1, unsigned a2, unsigned a3,
                                         unsigned b0, unsigned b1) {
    asm volatile(
        "mma.sync.aligned.m16n8k16.row.col.f32.bf16.bf16.f32 "
        "{%0,%1,%2,%3}, {%4,%5,%6,%7}, {%8,%9}, {%0,%1,%2,%3};"
        : "+f"(d.x), "+f"(d.y), "+f"(d.z), "+f"(d.w)
        : "r"(a0), "r"(a1), "r"(a2), "r"(a3), "r"(b0), "r"(b1));
}

__global__ __launch_bounds__(256) void k_gemm_hmma(
        const float* __restrict__ A,
        const __nv_bfloat16* __restrict__ WHT,
        const __nv_bfloat16* __restrict__ WLT,
        __half* __restrict__ C, int M, int scaled) {
    extern __shared__ unsigned sm[];
    unsigned* AH = sm + SM_AH;
    unsigned* AL = sm + SM_AL;
    unsigned* BH = sm + SM_BH;
    unsigned* BL = sm + SM_BL;

    int tid = threadIdx.x;
    int rowBase = blockIdx.x * 64;

    // ---- copy W tiles (bf16 [n][k] contiguous -> padded smem) ----
    {
        const uint4* gh = (const uint4*)WHT;
        const uint4* gl = (const uint4*)WLT;
        for (int i = tid; i < 2048; i += 256) {
            int nrow = i >> 4;
            int kk   = (i & 15) * 4;               // uint offset within row
            *(uint4*)&BH[nrow * AS + kk] = gh[i];
            *(uint4*)&BL[nrow * AS + kk] = gl[i];
        }
    }

    // ---- A tile: fp32 -> bf16 hi/lo into padded smem ----
    {
        int r  = tid >> 2;                          // 0..63
        int t4 = tid & 3;
        int rg = rowBase + r;
        const float4* A4 = (const float4*)A;
#pragma unroll
        for (int i = 0; i < 8; ++i) {
            float4 v = make_float4(0.f, 0.f, 0.f, 0.f);
            if (rg < M) v = A4[(size_t)rg * 32 + t4 * 8 + i];
            __nv_bfloat16 h0 = __float2bfloat16_rn(v.x), h1 = __float2bfloat16_rn(v.y);
            __nv_bfloat16 h2 = __float2bfloat16_rn(v.z), h3 = __float2bfloat16_rn(v.w);
            __nv_bfloat16 l0 = __float2bfloat16_rn(v.x - __bfloat162float(h0));
            __nv_bfloat16 l1 = __float2bfloat16_rn(v.y - __bfloat162float(h1));
            __nv_bfloat16 l2 = __float2bfloat16_rn(v.z - __bfloat162float(h2));
            __nv_bfloat16 l3 = __float2bfloat16_rn(v.w - __bfloat162float(h3));
            int w = r * AS + t4 * 16 + i * 2;       // uint index (col/2)
            AH[w]     = pack_bf2(h0, h1);
            AH[w + 1] = pack_bf2(h2, h3);
            AL[w]     = pack_bf2(l0, l1);
            AL[w + 1] = pack_bf2(l2, l3);
        }
    }
    __syncthreads();

    // ---- compute ----
    int wid = tid >> 5, lane = tid & 31;
    int wm = wid >> 1, wn = wid & 1;
    int g = lane >> 2, tig = lane & 3;

    float4 acc[8];
#pragma unroll
    for (int j = 0; j < 8; ++j) acc[j] = make_float4(0.f, 0.f, 0.f, 0.f);

    int ar0 = (wm * 16 + g) * AS;
    int ar1 = ar0 + 8 * AS;

#pragma unroll
    for (int ks = 0; ks < 8; ++ks) {
        int ka = ks * 8 + tig;
        unsigned ah0 = AH[ar0 + ka],     ah1 = AH[ar1 + ka];
        unsigned ah2 = AH[ar0 + ka + 4], ah3 = AH[ar1 + ka + 4];
        unsigned al0 = AL[ar0 + ka],     al1 = AL[ar1 + ka];
        unsigned al2 = AL[ar0 + ka + 4], al3 = AL[ar1 + ka + 4];
#pragma unroll
        for (int j = 0; j < 8; ++j) {
            int br = (wn * 64 + j * 8 + g) * AS + ka;
            unsigned bh0 = BH[br], bh1 = BH[br + 4];
            unsigned bl0 = BL[br], bl1 = BL[br + 4];
            mma_bf16(acc[j], ah0, ah1, ah2, ah3, bh0, bh1);
            mma_bf16(acc[j], al0, al1, al2, al3, bh0, bh1);
            mma_bf16(acc[j], ah0, ah1, ah2, ah3, bl0, bl1);
        }
    }

    // ---- epilogue: fp16 convert (+ optional dinv row scale), store ----
    int r0 = rowBase + wm * 16 + g;
    int r1 = r0 + 8;
    float s0 = 1.f, s1 = 1.f;
    if (scaled) {
        if (r0 < M) s0 = g_dinv[r0];
        if (r1 < M) s1 = g_dinv[r1];
    }
#pragma unroll
    for (int j = 0; j < 8; ++j) {
        int col = wn * 64 + j * 8 + tig * 2;
        if (r0 < M)
            *(__half2*)(C + (size_t)r0 * 128 + col) = __floats2half2_rn(acc[j].x * s0, acc[j].y * s0);
        if (r1 < M)
            *(__half2*)(C + (size_t)r1 * 128 + col) = __floats2half2_rn(acc[j].z * s1, acc[j].w * s1);
    }
}

// ---------------- scan: rowstart, cursors, dinv ----------------
__global__ void k_scan(int n) {
    __shared__ int part[1024];
    const int tid = threadIdx.x;
    const int chunk = (n + 1023) / 1024;
    const int beg = tid * chunk;
    const int end = min(beg + chunk, n);

    int s = 0;
    for (int i = beg; i < end; ++i) s += g_deg[i] - 1;
    part[tid] = s;
    __syncthreads();

    for (int off = 1; off < 1024; off <<= 1) {
        int v = (tid >= off) ? part[tid - off] : 0;
        __syncthreads();
        part[tid] += v;
        __syncthreads();
    }

    int run = (tid > 0) ? part[tid - 1] : 0;
    for (int i = beg; i < end; ++i) {
        int dg = g_deg[i];
        g_rowstart[i] = run;
        g_cur[i] = run;
        g_dinv[i] = rsqrtf((float)dg);
        run += dg - 1;
    }
}

// ---------------- CSR fill ----------------
__global__ void k_fill(const int* __restrict__ ei, int E) {
    int e = blockIdx.x * blockDim.x + threadIdx.x;
    if (e >= E) return;
    int s = load_idx(ei, (size_t)e);
    int d = load_idx(ei, (size_t)E + e);
    int pos = atomicAdd(&g_cur[d], 1);
    g_esrc[pos] = s;
}

// ---------------- aggregation (R7 version: best measured) -----------------
__device__ __forceinline__ void acc_h4(float4& acc, float nm, uint2 raw) {
    __half2* ph = (__half2*)&raw;
    float2 lo = __half22float2(ph[0]);
    float2 hi = __half22float2(ph[1]);
    acc.x = fmaf(nm, lo.x, acc.x); acc.y = fmaf(nm, lo.y, acc.y);
    acc.z = fmaf(nm, hi.x, acc.z); acc.w = fmaf(nm, hi.y, acc.w);
}
__device__ __forceinline__ void add_h4(float4& acc, uint2 raw) {
    __half2* ph = (__half2*)&raw;
    float2 lo = __half22float2(ph[0]);
    float2 hi = __half22float2(ph[1]);
    acc.x += lo.x; acc.y += lo.y; acc.z += hi.x; acc.w += hi.y;
}

template<bool SCALED>
__global__ void k_agg_csr(const __half* __restrict__ H,
                          const float* __restrict__ b,
                          float* __restrict__ out, int n) {
    int warp = (int)((blockIdx.x * (size_t)blockDim.x + threadIdx.x) >> 5);
    int lane = threadIdx.x & 31;
    if (warp >= n) return;
    int node = warp;

    const uint2* H2 = (const uint2*)H;
    float di = g_dinv[node];

    float4 acc = make_float4(0, 0, 0, 0);
    {
        uint2 raw = H2[(size_t)node * DH2 + lane];
        if (SCALED) add_h4(acc, raw);
        else        acc_h4(acc, di, raw);
    }

    int p   = g_rowstart[node];
    int end = p + (g_deg[node] - 1);

    for (; p + 3 < end; p += 4) {
        int s0 = g_esrc[p],   s1 = g_esrc[p+1];
        int s2 = g_esrc[p+2], s3 = g_esrc[p+3];
        uint2 v0 = H2[(size_t)s0 * DH2 + lane];
        uint2 v1 = H2[(size_t)s1 * DH2 + lane];
        uint2 v2 = H2[(size_t)s2 * DH2 + lane];
        uint2 v3 = H2[(size_t)s3 * DH2 + lane];
        if (SCALED) {
            add_h4(acc, v0); add_h4(acc, v1); add_h4(acc, v2); add_h4(acc, v3);
        } else {
            acc_h4(acc, g_dinv[s0], v0); acc_h4(acc, g_dinv[s1], v1);
            acc_h4(acc, g_dinv[s2], v2); acc_h4(acc, g_dinv[s3], v3);
        }
    }
    for (; p < end; ++p) {
        int s0 = g_esrc[p];
        uint2 v0 = H2[(size_t)s0 * DH2 + lane];
        if (SCALED) add_h4(acc, v0);
        else        acc_h4(acc, g_dinv[s0], v0);
    }

    float4 bv = ((const float4*)b)[lane];
    float4 r;
    r.x = fmaxf(fmaf(di, acc.x, bv.x), 0.f);
    r.y = fmaxf(fmaf(di, acc.y, bv.y), 0.f);
    r.z = fmaxf(fmaf(di, acc.z, bv.z), 0.f);
    r.w = fmaxf(fmaf(di, acc.w, bv.w), 0.f);
    ((float4*)out)[(size_t)node * D4 + lane] = r;
}

// ---------------- launch ----------------
extern "C" void kernel_launch(void* const* d_in, const int* in_sizes, int n_in,
                              void* d_out, int out_size) {
    const float* x  = (const float*)d_in[0];
    const int*   ei = (const int*)d_in[1];
    const float* W1 = (const float*)d_in[2];
    const float* b1 = (const float*)d_in[3];
    const float* W2 = (const float*)d_in[4];
    const float* b2 = (const float*)d_in[5];
    float* out = (float*)d_out;

    int n = in_sizes[0] / D;        // 50000
    int E = in_sizes[1] / 2;        // 800000

    __half* h;  float* a;
    __nv_bfloat16 *wh1, *wl1, *wh2, *wl2;
    cudaGetSymbolAddress((void**)&h,   g_h);
    cudaGetSymbolAddress((void**)&a,   g_a);
    cudaGetSymbolAddress((void**)&wh1, g_wh1);
    cudaGetSymbolAddress((void**)&wl1, g_wl1);
    cudaGetSymbolAddress((void**)&wh2, g_wh2);
    cudaGetSymbolAddress((void**)&wl2, g_wl2);

    cudaFuncSetAttribute(k_gemm_hmma, cudaFuncAttributeMaxDynamicSharedMemorySize,
                         SM_BYTES);

    int countBlocks = (E + 255) / 256;
    int aggBlocks   = (n * 32 + 255) / 256;
    int gemmBlocks  = (n + 63) / 64;

    k_init<<<(n + 255) / 256, 256>>>(ei, n);
    // W split/transpose + degree count in one launch
    k_pre<<<128 + countBlocks, 256>>>(W1, W2, ei, E);
    // layer-1 GEMM (HMMA tensor path, unscaled fp16 output)
    k_gemm_hmma<<<gemmBlocks, 256, SM_BYTES>>>(x, wh1, wl1, h, n, 0);
    k_scan<<<1, 1024>>>(n);
    k_fill<<<countBlocks, 256>>>(ei, E);
    // layer-1 aggregation (per-edge dinv)
    k_agg_csr<false><<<aggBlocks, 256>>>(h, b1, a, n);
    // layer-2 GEMM (epilogue scales rows by dinv) + pure gather-add agg
    k_gemm_hmma<<<gemmBlocks, 256, SM_BYTES>>>(a, wh2, wl2, h, n, 1);
    k_agg_csr<true><<<aggBlocks, 256>>>(h, b2, out, n);
}

// round 11
// speedup vs baseline: 2.1364x; 1.7310x over previous
#include <cuda_runtime.h>
#include <cuda_fp16.h>
#include <cuda_bf16.h>
#include <cstdint>

#define D 128
#define NMAX 50000
#define EMAX 800000
#define D4 (D/4)    // 32 float4 per fp32 row
#define DH2 (D/4)   // 32 uint2 per fp16 row

// ---------------- scratch (no allocations allowed) ----------------
__device__ int    g_deg[NMAX];
__device__ float  g_dinv[NMAX];
__device__ int    g_rowstart[NMAX];
__device__ int    g_cur[NMAX];
__device__ int    g_esrc[EMAX];
__device__ int    g_total;                 // CSR slot allocator
__device__ __half g_h[(size_t)NMAX * D];   // message buffer (fp16)
__device__ float  g_a[(size_t)NMAX * D];   // layer-1 activation (fp32)
__device__ int    g_is64;
// W split into bf16 hi/lo, TRANSPOSED: buf[n*128 + k] = bf16(W[k][n])
__device__ __align__(16) __nv_bfloat16 g_wh1[16384];
__device__ __align__(16) __nv_bfloat16 g_wl1[16384];
__device__ __align__(16) __nv_bfloat16 g_wh2[16384];
__device__ __align__(16) __nv_bfloat16 g_wl2[16384];

__device__ __forceinline__ int load_idx(const int* __restrict__ ei, size_t pos) {
    return g_is64 ? ei[2 * pos] : ei[pos];
}

__device__ __forceinline__ unsigned pack_bf2(__nv_bfloat16 lo, __nv_bfloat16 hi) {
    return ((unsigned)__bfloat16_as_ushort(hi) << 16) | __bfloat16_as_ushort(lo);
}

// ---------------- init degrees + dtype detect + counter reset -------------
__global__ void k_init(const int* __restrict__ ei, int n) {
    int i = blockIdx.x * blockDim.x + threadIdx.x;
    if (i < n) g_deg[i] = 1;
    if (blockIdx.x == 0 && threadIdx.x == 0) {
        g_total = 0;
        int all0 = 1;
        for (int j = 0; j < 64; ++j)
            if (ei[2 * j + 1] != 0) { all0 = 0; break; }
        g_is64 = all0;
    }
}

// ---------------- prep: W -> bf16 hi/lo transposed  +  degree count -------
__global__ void k_pre(const float* __restrict__ W1, const float* __restrict__ W2,
                      const int* __restrict__ ei, int E) {
    if (blockIdx.x < 128) {
        int mat = blockIdx.x >> 6;
        int idx = (blockIdx.x & 63) * 256 + threadIdx.x;
        if (idx < 16384) {
            const float* W = mat ? W2 : W1;
            __nv_bfloat16* WH = mat ? g_wh2 : g_wh1;
            __nv_bfloat16* WL = mat ? g_wl2 : g_wl1;
            int k = idx >> 7, j = idx & 127;
            float w = W[idx];                       // W[k][j]
            __nv_bfloat16 h = __float2bfloat16_rn(w);
            __nv_bfloat16 l = __float2bfloat16_rn(w - __bfloat162float(h));
            WH[j * 128 + k] = h;                    // transposed [n][k]
            WL[j * 128 + k] = l;
        }
    } else {
        int e = (blockIdx.x - 128) * blockDim.x + threadIdx.x;
        if (e < E) atomicAdd(&g_deg[load_idx(ei, (size_t)E + e)], 1);
    }
}

// ---------------- parallel CSR slot allocation + dinv ---------------------
// Replaces the 104us single-block scan. Rows only need DISJOINT ranges, not
// ordered ones: warp-prefix (shfl) + one atomicAdd per warp on g_total.
__global__ void k_alloc(int n) {
    int i    = blockIdx.x * blockDim.x + threadIdx.x;
    int lane = threadIdx.x & 31;
    int dg = (i < n) ? g_deg[i] : 1;
    int v  = dg - 1;

    int pfx = v;
#pragma unroll
    for (int o = 1; o < 32; o <<= 1) {
        int t = __shfl_up_sync(0xffffffff, pfx, o);
        if (lane >= o) pfx += t;
    }
    int wtotal = __shfl_sync(0xffffffff, pfx, 31);
    int excl   = pfx - v;

    int base = 0;
    if (lane == 31) base = atomicAdd(&g_total, wtotal);
    base = __shfl_sync(0xffffffff, base, 31);

    if (i < n) {
        int run = base + excl;
        g_rowstart[i] = run;
        g_cur[i]      = run;
        g_dinv[i]     = rsqrtf((float)dg);
    }
}

// ---------------- HMMA GEMM: C_fp16[M,128] = A_fp32[M,128] @ W ------------
#define AS 68                      // uint stride per smem row
#define SM_AH 0
#define SM_AL 4352                 // 64*68
#define SM_BH 8704
#define SM_BL 17408                // 8704 + 128*68
#define SM_UINTS 26112
#define SM_BYTES (SM_UINTS * 4)

__device__ __forceinline__ void mma_bf16(float4& d,
                                         unsigned a0, unsigned a1, unsigned a2, unsigned a3,
                                         unsigned b0, unsigned b1) {
    asm volatile(
        "mma.sync.aligned.m16n8k16.row.col.f32.bf16.bf16.f32 "
        "{%0,%1,%2,%3}, {%4,%5,%6,%7}, {%8,%9}, {%0,%1,%2,%3};"
        : "+f"(d.x), "+f"(d.y), "+f"(d.z), "+f"(d.w)
        : "r"(a0), "r"(a1), "r"(a2), "r"(a3), "r"(b0), "r"(b1));
}

__global__ __launch_bounds__(256) void k_gemm_hmma(
        const float* __restrict__ A,
        const __nv_bfloat16* __restrict__ WHT,
        const __nv_bfloat16* __restrict__ WLT,
        __half* __restrict__ C, int M, int scaled) {
    extern __shared__ unsigned sm[];
    unsigned* AH = sm + SM_AH;
    unsigned* AL = sm + SM_AL;
    unsigned* BH = sm + SM_BH;
    unsigned* BL = sm + SM_BL;

    int tid = threadIdx.x;
    int rowBase = blockIdx.x * 64;

    // ---- copy W tiles ----
    {
        const uint4* gh = (const uint4*)WHT;
        const uint4* gl = (const uint4*)WLT;
        for (int i = tid; i < 2048; i += 256) {
            int nrow = i >> 4;
            int kk   = (i & 15) * 4;
            *(uint4*)&BH[nrow * AS + kk] = gh[i];
            *(uint4*)&BL[nrow * AS + kk] = gl[i];
        }
    }

    // ---- A tile: fp32 -> bf16 hi/lo into padded smem ----
    {
        int r  = tid >> 2;
        int t4 = tid & 3;
        int rg = rowBase + r;
        const float4* A4 = (const float4*)A;
#pragma unroll
        for (int i = 0; i < 8; ++i) {
            float4 v = make_float4(0.f, 0.f, 0.f, 0.f);
            if (rg < M) v = A4[(size_t)rg * 32 + t4 * 8 + i];
            __nv_bfloat16 h0 = __float2bfloat16_rn(v.x), h1 = __float2bfloat16_rn(v.y);
            __nv_bfloat16 h2 = __float2bfloat16_rn(v.z), h3 = __float2bfloat16_rn(v.w);
            __nv_bfloat16 l0 = __float2bfloat16_rn(v.x - __bfloat162float(h0));
            __nv_bfloat16 l1 = __float2bfloat16_rn(v.y - __bfloat162float(h1));
            __nv_bfloat16 l2 = __float2bfloat16_rn(v.z - __bfloat162float(h2));
            __nv_bfloat16 l3 = __float2bfloat16_rn(v.w - __bfloat162float(h3));
            int w = r * AS + t4 * 16 + i * 2;
            AH[w]     = pack_bf2(h0, h1);
            AH[w + 1] = pack_bf2(h2, h3);
            AL[w]     = pack_bf2(l0, l1);
            AL[w + 1] = pack_bf2(l2, l3);
        }
    }
    __syncthreads();

    // ---- compute ----
    int wid = tid >> 5, lane = tid & 31;
    int wm = wid >> 1, wn = wid & 1;
    int g = lane >> 2, tig = lane & 3;

    float4 acc[8];
#pragma unroll
    for (int j = 0; j < 8; ++j) acc[j] = make_float4(0.f, 0.f, 0.f, 0.f);

    int ar0 = (wm * 16 + g) * AS;
    int ar1 = ar0 + 8 * AS;

#pragma unroll
    for (int ks = 0; ks < 8; ++ks) {
        int ka = ks * 8 + tig;
        unsigned ah0 = AH[ar0 + ka],     ah1 = AH[ar1 + ka];
        unsigned ah2 = AH[ar0 + ka + 4], ah3 = AH[ar1 + ka + 4];
        unsigned al0 = AL[ar0 + ka],     al1 = AL[ar1 + ka];
        unsigned al2 = AL[ar0 + ka + 4], al3 = AL[ar1 + ka + 4];
#pragma unroll
        for (int j = 0; j < 8; ++j) {
            int br = (wn * 64 + j * 8 + g) * AS + ka;
            unsigned bh0 = BH[br], bh1 = BH[br + 4];
            unsigned bl0 = BL[br], bl1 = BL[br + 4];
            mma_bf16(acc[j], ah0, ah1, ah2, ah3, bh0, bh1);
            mma_bf16(acc[j], al0, al1, al2, al3, bh0, bh1);
            mma_bf16(acc[j], ah0, ah1, ah2, ah3, bl0, bl1);
        }
    }

    // ---- epilogue ----
    int r0 = rowBase + wm * 16 + g;
    int r1 = r0 + 8;
    float s0 = 1.f, s1 = 1.f;
    if (scaled) {
        if (r0 < M) s0 = g_dinv[r0];
        if (r1 < M) s1 = g_dinv[r1];
    }
#pragma unroll
    for (int j = 0; j < 8; ++j) {
        int col = wn * 64 + j * 8 + tig * 2;
        if (r0 < M)
            *(__half2*)(C + (size_t)r0 * 128 + col) = __floats2half2_rn(acc[j].x * s0, acc[j].y * s0);
        if (r1 < M)
            *(__half2*)(C + (size_t)r1 * 128 + col) = __floats2half2_rn(acc[j].z * s1, acc[j].w * s1);
    }
}

// ---------------- CSR fill ----------------
__global__ void k_fill(const int* __restrict__ ei, int E) {
    int e = blockIdx.x * blockDim.x + threadIdx.x;
    if (e >= E) return;
    int s = load_idx(ei, (size_t)e);
    int d = load_idx(ei, (size_t)E + e);
    int pos = atomicAdd(&g_cur[d], 1);
    g_esrc[pos] = s;
}

// ---------------- aggregation (R7 version: best measured) -----------------
__device__ __forceinline__ void acc_h4(float4& acc, float nm, uint2 raw) {
    __half2* ph = (__half2*)&raw;
    float2 lo = __half22float2(ph[0]);
    float2 hi = __half22float2(ph[1]);
    acc.x = fmaf(nm, lo.x, acc.x); acc.y = fmaf(nm, lo.y, acc.y);
    acc.z = fmaf(nm, hi.x, acc.z); acc.w = fmaf(nm, hi.y, acc.w);
}
__device__ __forceinline__ void add_h4(float4& acc, uint2 raw) {
    __half2* ph = (__half2*)&raw;
    float2 lo = __half22float2(ph[0]);
    float2 hi = __half22float2(ph[1]);
    acc.x += lo.x; acc.y += lo.y; acc.z += hi.x; acc.w += hi.y;
}

template<bool SCALED>
__global__ void k_agg_csr(const __half* __restrict__ H,
                          const float* __restrict__ b,
                          float* __restrict__ out, int n) {
    int warp = (int)((blockIdx.x * (size_t)blockDim.x + threadIdx.x) >> 5);
    int lane = threadIdx.x & 31;
    if (warp >= n) return;
    int node = warp;

    const uint2* H2 = (const uint2*)H;
    float di = g_dinv[node];

    float4 acc = make_float4(0, 0, 0, 0);
    {
        uint2 raw = H2[(size_t)node * DH2 + lane];
        if (SCALED) add_h4(acc, raw);
        else        acc_h4(acc, di, raw);
    }

    int p   = g_rowstart[node];
    int end = p + (g_deg[node] - 1);

    for (; p + 3 < end; p += 4) {
        int s0 = g_esrc[p],   s1 = g_esrc[p+1];
        int s2 = g_esrc[p+2], s3 = g_esrc[p+3];
        uint2 v0 = H2[(size_t)s0 * DH2 + lane];
        uint2 v1 = H2[(size_t)s1 * DH2 + lane];
        uint2 v2 = H2[(size_t)s2 * DH2 + lane];
        uint2 v3 = H2[(size_t)s3 * DH2 + lane];
        if (SCALED) {
            add_h4(acc, v0); add_h4(acc, v1); add_h4(acc, v2); add_h4(acc, v3);
        } else {
            acc_h4(acc, g_dinv[s0], v0); acc_h4(acc, g_dinv[s1], v1);
            acc_h4(acc, g_dinv[s2], v2); acc_h4(acc, g_dinv[s3], v3);
        }
    }
    for (; p < end; ++p) {
        int s0 = g_esrc[p];
        uint2 v0 = H2[(size_t)s0 * DH2 + lane];
        if (SCALED) add_h4(acc, v0);
        else        acc_h4(acc, g_dinv[s0], v0);
    }

    float4 bv = ((const float4*)b)[lane];
    float4 r;
    r.x = fmaxf(fmaf(di, acc.x, bv.x), 0.f);
    r.y = fmaxf(fmaf(di, acc.y, bv.y), 0.f);
    r.z = fmaxf(fmaf(di, acc.z, bv.z), 0.f);
    r.w = fmaxf(fmaf(di, acc.w, bv.w), 0.f);
    ((float4*)out)[(size_t)node * D4 + lane] = r;
}

// ---------------- launch ----------------
extern "C" void kernel_launch(void* const* d_in, const int* in_sizes, int n_in,
                              void* d_out, int out_size) {
    const float* x  = (const float*)d_in[0];
    const int*   ei = (const int*)d_in[1];
    const float* W1 = (const float*)d_in[2];
    const float* b1 = (const float*)d_in[3];
    const float* W2 = (const float*)d_in[4];
    const float* b2 = (const float*)d_in[5];
    float* out = (float*)d_out;

    int n = in_sizes[0] / D;        // 50000
    int E = in_sizes[1] / 2;        // 800000

    __half* h;  float* a;
    __nv_bfloat16 *wh1, *wl1, *wh2, *wl2;
    cudaGetSymbolAddress((void**)&h,   g_h);
    cudaGetSymbolAddress((void**)&a,   g_a);
    cudaGetSymbolAddress((void**)&wh1, g_wh1);
    cudaGetSymbolAddress((void**)&wl1, g_wl1);
    cudaGetSymbolAddress((void**)&wh2, g_wh2);
    cudaGetSymbolAddress((void**)&wl2, g_wl2);

    cudaFuncSetAttribute(k_gemm_hmma, cudaFuncAttributeMaxDynamicSharedMemorySize,
                         SM_BYTES);

    int countBlocks = (E + 255) / 256;
    int aggBlocks   = (n * 32 + 255) / 256;
    int gemmBlocks  = (n + 63) / 64;
    int nodeBlocks  = (n + 255) / 256;

    k_init<<<nodeBlocks, 256>>>(ei, n);
    // W split/transpose + degree count in one launch
    k_pre<<<128 + countBlocks, 256>>>(W1, W2, ei, E);
    // layer-1 GEMM (HMMA, unscaled fp16 output)
    k_gemm_hmma<<<gemmBlocks, 256, SM_BYTES>>>(x, wh1, wl1, h, n, 0);
    // parallel CSR slot allocation (replaces 104us serial scan)
    k_alloc<<<nodeBlocks, 256>>>(n);
    k_fill<<<countBlocks, 256>>>(ei, E);
    // layer-1 aggregation (per-edge dinv)
    k_agg_csr<false><<<aggBlocks, 256>>>(h, b1, a, n);
    // layer-2 GEMM (epilogue scales rows by dinv) + pure gather-add agg
    k_gemm_hmma<<<gemmBlocks, 256, SM_BYTES>>>(a, wh2, wl2, h, n, 1);
    k_agg_csr<true><<<aggBlocks, 256>>>(h, b2, out, n);
}

// round 12
// speedup vs baseline: 2.1580x; 1.0101x over previous
#include <cuda_runtime.h>
#include <cuda_fp16.h>
#include <cuda_bf16.h>
#include <cstdint>

#define D 128
#define NMAX 50000
#define EMAX 800000
#define D4 (D/4)    // 32 float4 per fp32 row
#define DH2 (D/4)   // 32 uint2 per fp16 row

// ---------------- scratch (no allocations allowed) ----------------
__device__ int    g_deg[NMAX];
__device__ float  g_dinv[NMAX];
__device__ int    g_rowstart[NMAX];
__device__ int    g_cur[NMAX];
__device__ int    g_esrc[EMAX];
__device__ int    g_total;                 // CSR slot allocator
__device__ __half g_h[(size_t)NMAX * D];   // message buffer (fp16)
__device__ float  g_a[(size_t)NMAX * D];   // layer-1 activation (fp32)
__device__ int    g_is64;
// W split into bf16 hi/lo, TRANSPOSED: buf[n*128 + k] = bf16(W[k][n])
__device__ __align__(16) __nv_bfloat16 g_wh1[16384];
__device__ __align__(16) __nv_bfloat16 g_wl1[16384];
__device__ __align__(16) __nv_bfloat16 g_wh2[16384];
__device__ __align__(16) __nv_bfloat16 g_wl2[16384];

__device__ __forceinline__ int load_idx(const int* __restrict__ ei, size_t pos) {
    return g_is64 ? ei[2 * pos] : ei[pos];
}

__device__ __forceinline__ unsigned pack_bf2(__nv_bfloat16 lo, __nv_bfloat16 hi) {
    return ((unsigned)__bfloat16_as_ushort(hi) << 16) | __bfloat16_as_ushort(lo);
}

// ------ init degrees + dtype detect + counter reset + W hi/lo convert -----
__global__ void k_init(const int* __restrict__ ei,
                       const float* __restrict__ W1, const float* __restrict__ W2,
                       int n) {
    int i = blockIdx.x * blockDim.x + threadIdx.x;
    if (i < n) g_deg[i] = 1;
    // W conversion rides along: 32768 elements over the first 32768 threads
    if (i < 32768) {
        int mat = i >> 14;                  // 0: W1, 1: W2
        int idx = i & 16383;
        const float* W = mat ? W2 : W1;
        __nv_bfloat16* WH = mat ? g_wh2 : g_wh1;
        __nv_bfloat16* WL = mat ? g_wl2 : g_wl1;
        int k = idx >> 7, j = idx & 127;
        float w = W[idx];                   // W[k][j]
        __nv_bfloat16 h = __float2bfloat16_rn(w);
        __nv_bfloat16 l = __float2bfloat16_rn(w - __bfloat162float(h));
        WH[j * 128 + k] = h;                // transposed [n][k]
        WL[j * 128 + k] = l;
    }
    if (blockIdx.x == 0 && threadIdx.x == 0) {
        g_total = 0;
        int all0 = 1;
        for (int j = 0; j < 64; ++j)
            if (ei[2 * j + 1] != 0) { all0 = 0; break; }
        g_is64 = all0;
    }
}

// ---------------- HMMA GEMM body ----------------
#define AS 68                      // uint stride per smem row
#define SM_AH 0
#define SM_AL 4352                 // 64*68
#define SM_BH 8704
#define SM_BL 17408                // 8704 + 128*68
#define SM_UINTS 26112
#define SM_BYTES (SM_UINTS * 4)

__device__ __forceinline__ void mma_bf16(float4& d,
                                         unsigned a0, unsigned a1, unsigned a2, unsigned a3,
                                         unsigned b0, unsigned b1) {
    asm volatile(
        "mma.sync.aligned.m16n8k16.row.col.f32.bf16.bf16.f32 "
        "{%0,%1,%2,%3}, {%4,%5,%6,%7}, {%8,%9}, {%0,%1,%2,%3};"
        : "+f"(d.x), "+f"(d.y), "+f"(d.z), "+f"(d.w)
        : "r"(a0), "r"(a1), "r"(a2), "r"(a3), "r"(b0), "r"(b1));
}

__device__ __forceinline__ void gemm_body(
        int bid, unsigned* sm,
        const float* __restrict__ A,
        const __nv_bfloat16* __restrict__ WHT,
        const __nv_bfloat16* __restrict__ WLT,
        __half* __restrict__ C, int M, int scaled) {
    unsigned* AH = sm + SM_AH;
    unsigned* AL = sm + SM_AL;
    unsigned* BH = sm + SM_BH;
    unsigned* BL = sm + SM_BL;

    int tid = threadIdx.x;
    int rowBase = bid * 64;

    // ---- copy W tiles ----
    {
        const uint4* gh = (const uint4*)WHT;
        const uint4* gl = (const uint4*)WLT;
        for (int i = tid; i < 2048; i += 256) {
            int nrow = i >> 4;
            int kk   = (i & 15) * 4;
            *(uint4*)&BH[nrow * AS + kk] = gh[i];
            *(uint4*)&BL[nrow * AS + kk] = gl[i];
        }
    }

    // ---- A tile: fp32 -> bf16 hi/lo into padded smem ----
    {
        int r  = tid >> 2;
        int t4 = tid & 3;
        int rg = rowBase + r;
        const float4* A4 = (const float4*)A;
#pragma unroll
        for (int i = 0; i < 8; ++i) {
            float4 v = make_float4(0.f, 0.f, 0.f, 0.f);
            if (rg < M) v = A4[(size_t)rg * 32 + t4 * 8 + i];
            __nv_bfloat16 h0 = __float2bfloat16_rn(v.x), h1 = __float2bfloat16_rn(v.y);
            __nv_bfloat16 h2 = __float2bfloat16_rn(v.z), h3 = __float2bfloat16_rn(v.w);
            __nv_bfloat16 l0 = __float2bfloat16_rn(v.x - __bfloat162float(h0));
            __nv_bfloat16 l1 = __float2bfloat16_rn(v.y - __bfloat162float(h1));
            __nv_bfloat16 l2 = __float2bfloat16_rn(v.z - __bfloat162float(h2));
            __nv_bfloat16 l3 = __float2bfloat16_rn(v.w - __bfloat162float(h3));
            int w = r * AS + t4 * 16 + i * 2;
            AH[w]     = pack_bf2(h0, h1);
            AH[w + 1] = pack_bf2(h2, h3);
            AL[w]     = pack_bf2(l0, l1);
            AL[w + 1] = pack_bf2(l2, l3);
        }
    }
    __syncthreads();

    // ---- compute ----
    int wid = tid >> 5, lane = tid & 31;
    int wm = wid >> 1, wn = wid & 1;
    int g = lane >> 2, tig = lane & 3;

    float4 acc[8];
#pragma unroll
    for (int j = 0; j < 8; ++j) acc[j] = make_float4(0.f, 0.f, 0.f, 0.f);

    int ar0 = (wm * 16 + g) * AS;
    int ar1 = ar0 + 8 * AS;

#pragma unroll
    for (int ks = 0; ks < 8; ++ks) {
        int ka = ks * 8 + tig;
        unsigned ah0 = AH[ar0 + ka],     ah1 = AH[ar1 + ka];
        unsigned ah2 = AH[ar0 + ka + 4], ah3 = AH[ar1 + ka + 4];
        unsigned al0 = AL[ar0 + ka],     al1 = AL[ar1 + ka];
        unsigned al2 = AL[ar0 + ka + 4], al3 = AL[ar1 + ka + 4];
#pragma unroll
        for (int j = 0; j < 8; ++j) {
            int br = (wn * 64 + j * 8 + g) * AS + ka;
            unsigned bh0 = BH[br], bh1 = BH[br + 4];
            unsigned bl0 = BL[br], bl1 = BL[br + 4];
            mma_bf16(acc[j], ah0, ah1, ah2, ah3, bh0, bh1);
            mma_bf16(acc[j], al0, al1, al2, al3, bh0, bh1);
            mma_bf16(acc[j], ah0, ah1, ah2, ah3, bl0, bl1);
        }
    }

    // ---- epilogue ----
    int r0 = rowBase + wm * 16 + g;
    int r1 = r0 + 8;
    float s0 = 1.f, s1 = 1.f;
    if (scaled) {
        if (r0 < M) s0 = g_dinv[r0];
        if (r1 < M) s1 = g_dinv[r1];
    }
#pragma unroll
    for (int j = 0; j < 8; ++j) {
        int col = wn * 64 + j * 8 + tig * 2;
        if (r0 < M)
            *(__half2*)(C + (size_t)r0 * 128 + col) = __floats2half2_rn(acc[j].x * s0, acc[j].y * s0);
        if (r1 < M)
            *(__half2*)(C + (size_t)r1 * 128 + col) = __floats2half2_rn(acc[j].z * s1, acc[j].w * s1);
    }
}

// ---------------- mega: GEMM1 blocks + degree-count blocks ----------------
// GEMM1 is tensor/smem-bound, count is L2-atomic-bound: count hides behind gemm.
__global__ __launch_bounds__(256) void k_mega(
        const float* __restrict__ A,
        const __nv_bfloat16* __restrict__ WHT,
        const __nv_bfloat16* __restrict__ WLT,
        __half* __restrict__ C, int M,
        const int* __restrict__ ei, int E, int gemmBlocks) {
    extern __shared__ unsigned sm[];
    if ((int)blockIdx.x < gemmBlocks) {
        gemm_body(blockIdx.x, sm, A, WHT, WLT, C, M, 0);
    } else {
        int e = (blockIdx.x - gemmBlocks) * blockDim.x + threadIdx.x;
        if (e < E) atomicAdd(&g_deg[load_idx(ei, (size_t)E + e)], 1);
    }
}

__global__ __launch_bounds__(256) void k_gemm2(
        const float* __restrict__ A,
        const __nv_bfloat16* __restrict__ WHT,
        const __nv_bfloat16* __restrict__ WLT,
        __half* __restrict__ C, int M) {
    extern __shared__ unsigned sm[];
    gemm_body(blockIdx.x, sm, A, WHT, WLT, C, M, 1);
}

// ---------------- parallel CSR slot allocation + dinv ---------------------
__global__ void k_alloc(int n) {
    int i    = blockIdx.x * blockDim.x + threadIdx.x;
    int lane = threadIdx.x & 31;
    int dg = (i < n) ? g_deg[i] : 1;
    int v  = dg - 1;

    int pfx = v;
#pragma unroll
    for (int o = 1; o < 32; o <<= 1) {
        int t = __shfl_up_sync(0xffffffff, pfx, o);
        if (lane >= o) pfx += t;
    }
    int wtotal = __shfl_sync(0xffffffff, pfx, 31);
    int excl   = pfx - v;

    int base = 0;
    if (lane == 31) base = atomicAdd(&g_total, wtotal);
    base = __shfl_sync(0xffffffff, base, 31);

    if (i < n) {
        int run = base + excl;
        g_rowstart[i] = run;
        g_cur[i]      = run;
        g_dinv[i]     = rsqrtf((float)dg);
    }
}

// ---------------- CSR fill ----------------
__global__ void k_fill(const int* __restrict__ ei, int E) {
    int e = blockIdx.x * blockDim.x + threadIdx.x;
    if (e >= E) return;
    int s = load_idx(ei, (size_t)e);
    int d = load_idx(ei, (size_t)E + e);
    int pos = atomicAdd(&g_cur[d], 1);
    g_esrc[pos] = s;
}

// ---------------- aggregation (best measured config) ----------------------
__device__ __forceinline__ void acc_h4(float4& acc, float nm, uint2 raw) {
    __half2* ph = (__half2*)&raw;
    float2 lo = __half22float2(ph[0]);
    float2 hi = __half22float2(ph[1]);
    acc.x = fmaf(nm, lo.x, acc.x); acc.y = fmaf(nm, lo.y, acc.y);
    acc.z = fmaf(nm, hi.x, acc.z); acc.w = fmaf(nm, hi.y, acc.w);
}
__device__ __forceinline__ void add_h4(float4& acc, uint2 raw) {
    __half2* ph = (__half2*)&raw;
    float2 lo = __half22float2(ph[0]);
    float2 hi = __half22float2(ph[1]);
    acc.x += lo.x; acc.y += lo.y; acc.z += hi.x; acc.w += hi.y;
}

template<bool SCALED>
__global__ void k_agg_csr(const __half* __restrict__ H,
                          const float* __restrict__ b,
                          float* __restrict__ out, int n) {
    int warp = (int)((blockIdx.x * (size_t)blockDim.x + threadIdx.x) >> 5);
    int lane = threadIdx.x & 31;
    if (warp >= n) return;
    int node = warp;

    const uint2* H2 = (const uint2*)H;
    float di = g_dinv[node];

    float4 acc = make_float4(0, 0, 0, 0);
    {
        uint2 raw = H2[(size_t)node * DH2 + lane];
        if (SCALED) add_h4(acc, raw);
        else        acc_h4(acc, di, raw);
    }

    int p   = g_rowstart[node];
    int end = p + (g_deg[node] - 1);

    for (; p + 3 < end; p += 4) {
        int s0 = g_esrc[p],   s1 = g_esrc[p+1];
        int s2 = g_esrc[p+2], s3 = g_esrc[p+3];
        uint2 v0 = H2[(size_t)s0 * DH2 + lane];
        uint2 v1 = H2[(size_t)s1 * DH2 + lane];
        uint2 v2 = H2[(size_t)s2 * DH2 + lane];
        uint2 v3 = H2[(size_t)s3 * DH2 + lane];
        if (SCALED) {
            add_h4(acc, v0); add_h4(acc, v1); add_h4(acc, v2); add_h4(acc, v3);
        } else {
            acc_h4(acc, g_dinv[s0], v0); acc_h4(acc, g_dinv[s1], v1);
            acc_h4(acc, g_dinv[s2], v2); acc_h4(acc, g_dinv[s3], v3);
        }
    }
    for (; p < end; ++p) {
        int s0 = g_esrc[p];
        uint2 v0 = H2[(size_t)s0 * DH2 + lane];
        if (SCALED) add_h4(acc, v0);
        else        acc_h4(acc, g_dinv[s0], v0);
    }

    float4 bv = ((const float4*)b)[lane];
    float4 r;
    r.x = fmaxf(fmaf(di, acc.x, bv.x), 0.f);
    r.y = fmaxf(fmaf(di, acc.y, bv.y), 0.f);
    r.z = fmaxf(fmaf(di, acc.z, bv.z), 0.f);
    r.w = fmaxf(fmaf(di, acc.w, bv.w), 0.f);
    ((float4*)out)[(size_t)node * D4 + lane] = r;
}

// ---------------- launch ----------------
extern "C" void kernel_launch(void* const* d_in, const int* in_sizes, int n_in,
                              void* d_out, int out_size) {
    const float* x  = (const float*)d_in[0];
    const int*   ei = (const int*)d_in[1];
    const float* W1 = (const float*)d_in[2];
    const float* b1 = (const float*)d_in[3];
    const float* W2 = (const float*)d_in[4];
    const float* b2 = (const float*)d_in[5];
    float* out = (float*)d_out;

    int n = in_sizes[0] / D;        // 50000
    int E = in_sizes[1] / 2;        // 800000

    __half* h;  float* a;
    __nv_bfloat16 *wh1, *wl1, *wh2, *wl2;
    cudaGetSymbolAddress((void**)&h,   g_h);
    cudaGetSymbolAddress((void**)&a,   g_a);
    cudaGetSymbolAddress((void**)&wh1, g_wh1);
    cudaGetSymbolAddress((void**)&wl1, g_wl1);
    cudaGetSymbolAddress((void**)&wh2, g_wh2);
    cudaGetSymbolAddress((void**)&wl2, g_wl2);

    cudaFuncSetAttribute(k_mega,  cudaFuncAttributeMaxDynamicSharedMemorySize, SM_BYTES);
    cudaFuncSetAttribute(k_gemm2, cudaFuncAttributeMaxDynamicSharedMemorySize, SM_BYTES);

    int countBlocks = (E + 255) / 256;
    int aggBlocks   = (n * 32 + 255) / 256;
    int gemmBlocks  = (n + 63) / 64;
    int nodeBlocks  = (n + 255) / 256;

    // deg init + dtype detect + W hi/lo conversion
    k_init<<<nodeBlocks, 256>>>(ei, W1, W2, n);
    // GEMM1 overlapped with degree count
    k_mega<<<gemmBlocks + countBlocks, 256, SM_BYTES>>>(x, wh1, wl1, h, n, ei, E, gemmBlocks);
    // parallel CSR slot allocation
    k_alloc<<<nodeBlocks, 256>>>(n);
    k_fill<<<countBlocks, 256>>>(ei, E);
    // layer-1 aggregation (per-edge dinv)
    k_agg_csr<false><<<aggBlocks, 256>>>(h, b1, a, n);
    // layer-2 GEMM (epilogue scales rows by dinv) + pure gather-add agg
    k_gemm2<<<gemmBlocks, 256, SM_BYTES>>>(a, wh2, wl2, h, n);
    k_agg_csr<true><<<aggBlocks, 256>>>(h, b2, out, n);
}

// round 13
// speedup vs baseline: 2.1616x; 1.0017x over previous
#include <cuda_runtime.h>
#include <cuda_fp16.h>
#include <cuda_bf16.h>
#include <cstdint>

#define D 128
#define NMAX 50000
#define EMAX 800000
#define D4 (D/4)    // 32 float4 per fp32 row
#define DH2 (D/4)   // 32 uint2 per fp16 row

// ---------------- scratch (no allocations allowed) ----------------
__device__ int    g_deg[NMAX];
__device__ float  g_dinv[NMAX];
__device__ int    g_rowstart[NMAX];
__device__ int    g_cur[NMAX];
__device__ int    g_esrc[EMAX];
__device__ int    g_total;                 // CSR slot allocator
__device__ __half g_h[(size_t)NMAX * D];   // message buffer (fp16)
__device__ float  g_a[(size_t)NMAX * D];   // layer-1 activation (fp32)
__device__ int    g_is64;
// W split into bf16 hi/lo, TRANSPOSED: buf[n*128 + k] = bf16(W[k][n])
__device__ __align__(16) __nv_bfloat16 g_wh1[16384];
__device__ __align__(16) __nv_bfloat16 g_wl1[16384];
__device__ __align__(16) __nv_bfloat16 g_wh2[16384];
__device__ __align__(16) __nv_bfloat16 g_wl2[16384];

__device__ __forceinline__ int load_idx(const int* __restrict__ ei, size_t pos) {
    return g_is64 ? ei[2 * pos] : ei[pos];
}

__device__ __forceinline__ unsigned pack_bf2(__nv_bfloat16 lo, __nv_bfloat16 hi) {
    return ((unsigned)__bfloat16_as_ushort(hi) << 16) | __bfloat16_as_ushort(lo);
}

// ------ init degrees + dtype detect + counter reset + W hi/lo convert -----
__global__ void k_init(const int* __restrict__ ei,
                       const float* __restrict__ W1, const float* __restrict__ W2,
                       int n) {
    int i = blockIdx.x * blockDim.x + threadIdx.x;
    if (i < n) g_deg[i] = 1;
    if (i < 32768) {
        int mat = i >> 14;                  // 0: W1, 1: W2
        int idx = i & 16383;
        const float* W = mat ? W2 : W1;
        __nv_bfloat16* WH = mat ? g_wh2 : g_wh1;
        __nv_bfloat16* WL = mat ? g_wl2 : g_wl1;
        int k = idx >> 7, j = idx & 127;
        float w = W[idx];                   // W[k][j]
        __nv_bfloat16 h = __float2bfloat16_rn(w);
        __nv_bfloat16 l = __float2bfloat16_rn(w - __bfloat162float(h));
        WH[j * 128 + k] = h;                // transposed [n][k]
        WL[j * 128 + k] = l;
    }
    if (blockIdx.x == 0 && threadIdx.x == 0) {
        g_total = 0;
        int all0 = 1;
        for (int j = 0; j < 64; ++j)
            if (ei[2 * j + 1] != 0) { all0 = 0; break; }
        g_is64 = all0;
    }
}

// ---------------- HMMA GEMM body (2m x 4n warp grid) ----------------
#define AS 68                      // uint stride per smem row
#define SM_AH 0
#define SM_AL 4352                 // 64*68
#define SM_BH 8704
#define SM_BL 17408                // 8704 + 128*68
#define SM_UINTS 26112
#define SM_BYTES (SM_UINTS * 4)

__device__ __forceinline__ void mma_bf16(float4& d,
                                         unsigned a0, unsigned a1, unsigned a2, unsigned a3,
                                         unsigned b0, unsigned b1) {
    asm volatile(
        "mma.sync.aligned.m16n8k16.row.col.f32.bf16.bf16.f32 "
        "{%0,%1,%2,%3}, {%4,%5,%6,%7}, {%8,%9}, {%0,%1,%2,%3};"
        : "+f"(d.x), "+f"(d.y), "+f"(d.z), "+f"(d.w)
        : "r"(a0), "r"(a1), "r"(a2), "r"(a3), "r"(b0), "r"(b1));
}

__device__ __forceinline__ void gemm_body(
        int bid, unsigned* sm,
        const float* __restrict__ A,
        const __nv_bfloat16* __restrict__ WHT,
        const __nv_bfloat16* __restrict__ WLT,
        __half* __restrict__ C, int M, int scaled) {
    unsigned* AH = sm + SM_AH;
    unsigned* AL = sm + SM_AL;
    unsigned* BH = sm + SM_BH;
    unsigned* BL = sm + SM_BL;

    int tid = threadIdx.x;
    int rowBase = bid * 64;

    // ---- copy W tiles ----
    {
        const uint4* gh = (const uint4*)WHT;
        const uint4* gl = (const uint4*)WLT;
        for (int i = tid; i < 2048; i += 256) {
            int nrow = i >> 4;
            int kk   = (i & 15) * 4;
            *(uint4*)&BH[nrow * AS + kk] = gh[i];
            *(uint4*)&BL[nrow * AS + kk] = gl[i];
        }
    }

    // ---- A tile: fp32 -> bf16 hi/lo into padded smem ----
    {
        int r  = tid >> 2;
        int t4 = tid & 3;
        int rg = rowBase + r;
        const float4* A4 = (const float4*)A;
#pragma unroll
        for (int i = 0; i < 8; ++i) {
            float4 v = make_float4(0.f, 0.f, 0.f, 0.f);
            if (rg < M) v = A4[(size_t)rg * 32 + t4 * 8 + i];
            __nv_bfloat16 h0 = __float2bfloat16_rn(v.x), h1 = __float2bfloat16_rn(v.y);
            __nv_bfloat16 h2 = __float2bfloat16_rn(v.z), h3 = __float2bfloat16_rn(v.w);
            __nv_bfloat16 l0 = __float2bfloat16_rn(v.x - __bfloat162float(h0));
            __nv_bfloat16 l1 = __float2bfloat16_rn(v.y - __bfloat162float(h1));
            __nv_bfloat16 l2 = __float2bfloat16_rn(v.z - __bfloat162float(h2));
            __nv_bfloat16 l3 = __float2bfloat16_rn(v.w - __bfloat162float(h3));
            int w = r * AS + t4 * 16 + i * 2;
            AH[w]     = pack_bf2(h0, h1);
            AH[w + 1] = pack_bf2(h2, h3);
            AL[w]     = pack_bf2(l0, l1);
            AL[w + 1] = pack_bf2(l2, l3);
        }
    }
    __syncthreads();

    // ---- compute: warp grid 2m x 4n, warp tile = 32 rows x 32 cols ----
    int wid = tid >> 5, lane = tid & 31;
    int wm = wid & 1, wn = wid >> 1;          // wm: 0..1, wn: 0..3
    int g = lane >> 2, tig = lane & 3;

    float4 acc[2][4];
#pragma unroll
    for (int mt = 0; mt < 2; ++mt)
#pragma unroll
        for (int nt = 0; nt < 4; ++nt) acc[mt][nt] = make_float4(0.f, 0.f, 0.f, 0.f);

#pragma unroll
    for (int ks = 0; ks < 8; ++ks) {
        int ka = ks * 8 + tig;
        unsigned ah[2][4], al[2][4];
#pragma unroll
        for (int mt = 0; mt < 2; ++mt) {
            int ar0 = (wm * 32 + mt * 16 + g) * AS;
            int ar1 = ar0 + 8 * AS;
            ah[mt][0] = AH[ar0 + ka];     ah[mt][1] = AH[ar1 + ka];
            ah[mt][2] = AH[ar0 + ka + 4]; ah[mt][3] = AH[ar1 + ka + 4];
            al[mt][0] = AL[ar0 + ka];     al[mt][1] = AL[ar1 + ka];
            al[mt][2] = AL[ar0 + ka + 4]; al[mt][3] = AL[ar1 + ka + 4];
        }
        unsigned bh[4][2], bl[4][2];
#pragma unroll
        for (int nt = 0; nt < 4; ++nt) {
            int br = (wn * 32 + nt * 8 + g) * AS + ka;
            bh[nt][0] = BH[br]; bh[nt][1] = BH[br + 4];
            bl[nt][0] = BL[br]; bl[nt][1] = BL[br + 4];
        }
#pragma unroll
        for (int mt = 0; mt < 2; ++mt)
#pragma unroll
            for (int nt = 0; nt < 4; ++nt) {
                mma_bf16(acc[mt][nt], ah[mt][0], ah[mt][1], ah[mt][2], ah[mt][3],
                         bh[nt][0], bh[nt][1]);
                mma_bf16(acc[mt][nt], al[mt][0], al[mt][1], al[mt][2], al[mt][3],
                         bh[nt][0], bh[nt][1]);
                mma_bf16(acc[mt][nt], ah[mt][0], ah[mt][1], ah[mt][2], ah[mt][3],
                         bl[nt][0], bl[nt][1]);
            }
    }

    // ---- epilogue ----
#pragma unroll
    for (int mt = 0; mt < 2; ++mt) {
        int r0 = rowBase + wm * 32 + mt * 16 + g;
        int r1 = r0 + 8;
        float s0 = 1.f, s1 = 1.f;
        if (scaled) {
            if (r0 < M) s0 = g_dinv[r0];
            if (r1 < M) s1 = g_dinv[r1];
        }
#pragma unroll
        for (int nt = 0; nt < 4; ++nt) {
            int col = wn * 32 + nt * 8 + tig * 2;
            if (r0 < M)
                *(__half2*)(C + (size_t)r0 * 128 + col) =
                    __floats2half2_rn(acc[mt][nt].x * s0, acc[mt][nt].y * s0);
            if (r1 < M)
                *(__half2*)(C + (size_t)r1 * 128 + col) =
                    __floats2half2_rn(acc[mt][nt].z * s1, acc[mt][nt].w * s1);
        }
    }
}

// ---------------- mega: GEMM1 blocks + degree-count blocks ----------------
__global__ __launch_bounds__(256) void k_mega(
        const float* __restrict__ A,
        const __nv_bfloat16* __restrict__ WHT,
        const __nv_bfloat16* __restrict__ WLT,
        __half* __restrict__ C, int M,
        const int* __restrict__ ei, int E, int gemmBlocks) {
    extern __shared__ unsigned sm[];
    if ((int)blockIdx.x < gemmBlocks) {
        gemm_body(blockIdx.x, sm, A, WHT, WLT, C, M, 0);
    } else {
        int e = (blockIdx.x - gemmBlocks) * blockDim.x + threadIdx.x;
        if (e < E) atomicAdd(&g_deg[load_idx(ei, (size_t)E + e)], 1);
    }
}

__global__ __launch_bounds__(256) void k_gemm2(
        const float* __restrict__ A,
        const __nv_bfloat16* __restrict__ WHT,
        const __nv_bfloat16* __restrict__ WLT,
        __half* __restrict__ C, int M) {
    extern __shared__ unsigned sm[];
    gemm_body(blockIdx.x, sm, A, WHT, WLT, C, M, 1);
}

// ---------------- parallel CSR slot allocation + dinv ---------------------
__global__ void k_alloc(int n) {
    int i    = blockIdx.x * blockDim.x + threadIdx.x;
    int lane = threadIdx.x & 31;
    int dg = (i < n) ? g_deg[i] : 1;
    int v  = dg - 1;

    int pfx = v;
#pragma unroll
    for (int o = 1; o < 32; o <<= 1) {
        int t = __shfl_up_sync(0xffffffff, pfx, o);
        if (lane >= o) pfx += t;
    }
    int wtotal = __shfl_sync(0xffffffff, pfx, 31);
    int excl   = pfx - v;

    int base = 0;
    if (lane == 31) base = atomicAdd(&g_total, wtotal);
    base = __shfl_sync(0xffffffff, base, 31);

    if (i < n) {
        int run = base + excl;
        g_rowstart[i] = run;
        g_cur[i]      = run;
        g_dinv[i]     = rsqrtf((float)dg);
    }
}

// ---------------- CSR fill: 4 edges per thread for atomic ILP -------------
__global__ void k_fill(const int* __restrict__ ei, int E) {
    int t = blockIdx.x * blockDim.x + threadIdx.x;
    int e0 = t * 4;
#pragma unroll
    for (int q = 0; q < 4; ++q) {
        int e = e0 + q;
        if (e < E) {
            int s = load_idx(ei, (size_t)e);
            int d = load_idx(ei, (size_t)E + e);
            int pos = atomicAdd(&g_cur[d], 1);
            g_esrc[pos] = s;
        }
    }
}

// ---------------- aggregation (best measured config) ----------------------
__device__ __forceinline__ void acc_h4(float4& acc, float nm, uint2 raw) {
    __half2* ph = (__half2*)&raw;
    float2 lo = __half22float2(ph[0]);
    float2 hi = __half22float2(ph[1]);
    acc.x = fmaf(nm, lo.x, acc.x); acc.y = fmaf(nm, lo.y, acc.y);
    acc.z = fmaf(nm, hi.x, acc.z); acc.w = fmaf(nm, hi.y, acc.w);
}
__device__ __forceinline__ void add_h4(float4& acc, uint2 raw) {
    __half2* ph = (__half2*)&raw;
    float2 lo = __half22float2(ph[0]);
    float2 hi = __half22float2(ph[1]);
    acc.x += lo.x; acc.y += lo.y; acc.z += hi.x; acc.w += hi.y;
}

template<bool SCALED>
__global__ void k_agg_csr(const __half* __restrict__ H,
                          const float* __restrict__ b,
                          float* __restrict__ out, int n) {
    int warp = (int)((blockIdx.x * (size_t)blockDim.x + threadIdx.x) >> 5);
    int lane = threadIdx.x & 31;
    if (warp >= n) return;
    int node = warp;

    const uint2* H2 = (const uint2*)H;
    float di = g_dinv[node];

    float4 acc = make_float4(0, 0, 0, 0);
    {
        uint2 raw = H2[(size_t)node * DH2 + lane];
        if (SCALED) add_h4(acc, raw);
        else        acc_h4(acc, di, raw);
    }

    int p   = g_rowstart[node];
    int end = p + (g_deg[node] - 1);

    for (; p + 3 < end; p += 4) {
        int s0 = g_esrc[p],   s1 = g_esrc[p+1];
        int s2 = g_esrc[p+2], s3 = g_esrc[p+3];
        uint2 v0 = H2[(size_t)s0 * DH2 + lane];
        uint2 v1 = H2[(size_t)s1 * DH2 + lane];
        uint2 v2 = H2[(size_t)s2 * DH2 + lane];
        uint2 v3 = H2[(size_t)s3 * DH2 + lane];
        if (SCALED) {
            add_h4(acc, v0); add_h4(acc, v1); add_h4(acc, v2); add_h4(acc, v3);
        } else {
            acc_h4(acc, g_dinv[s0], v0); acc_h4(acc, g_dinv[s1], v1);
            acc_h4(acc, g_dinv[s2], v2); acc_h4(acc, g_dinv[s3], v3);
        }
    }
    for (; p < end; ++p) {
        int s0 = g_esrc[p];
        uint2 v0 = H2[(size_t)s0 * DH2 + lane];
        if (SCALED) add_h4(acc, v0);
        else        acc_h4(acc, g_dinv[s0], v0);
    }

    float4 bv = ((const float4*)b)[lane];
    float4 r;
    r.x = fmaxf(fmaf(di, acc.x, bv.x), 0.f);
    r.y = fmaxf(fmaf(di, acc.y, bv.y), 0.f);
    r.z = fmaxf(fmaf(di, acc.z, bv.z), 0.f);
    r.w = fmaxf(fmaf(di, acc.w, bv.w), 0.f);
    ((float4*)out)[(size_t)node * D4 + lane] = r;
}

// ---------------- launch ----------------
extern "C" void kernel_launch(void* const* d_in, const int* in_sizes, int n_in,
                              void* d_out, int out_size) {
    const float* x  = (const float*)d_in[0];
    const int*   ei = (const int*)d_in[1];
    const float* W1 = (const float*)d_in[2];
    const float* b1 = (const float*)d_in[3];
    const float* W2 = (const float*)d_in[4];
    const float* b2 = (const float*)d_in[5];
    float* out = (float*)d_out;

    int n = in_sizes[0] / D;        // 50000
    int E = in_sizes[1] / 2;        // 800000

    __half* h;  float* a;
    __nv_bfloat16 *wh1, *wl1, *wh2, *wl2;
    cudaGetSymbolAddress((void**)&h,   g_h);
    cudaGetSymbolAddress((void**)&a,   g_a);
    cudaGetSymbolAddress((void**)&wh1, g_wh1);
    cudaGetSymbolAddress((void**)&wl1, g_wl1);
    cudaGetSymbolAddress((void**)&wh2, g_wh2);
    cudaGetSymbolAddress((void**)&wl2, g_wl2);

    cudaFuncSetAttribute(k_mega,  cudaFuncAttributeMaxDynamicSharedMemorySize, SM_BYTES);
    cudaFuncSetAttribute(k_gemm2, cudaFuncAttributeMaxDynamicSharedMemorySize, SM_BYTES);

    int countBlocks = (E + 255) / 256;
    int fillBlocks  = (E + 1023) / 1024;   // 4 edges per thread
    int aggBlocks   = (n * 32 + 255) / 256;
    int gemmBlocks  = (n + 63) / 64;
    int nodeBlocks  = (n + 255) / 256;

    // deg init + dtype detect + W hi/lo conversion
    k_init<<<nodeBlocks, 256>>>(ei, W1, W2, n);
    // GEMM1 overlapped with degree count
    k_mega<<<gemmBlocks + countBlocks, 256, SM_BYTES>>>(x, wh1, wl1, h, n, ei, E, gemmBlocks);
    // parallel CSR slot allocation
    k_alloc<<<nodeBlocks, 256>>>(n);
    k_fill<<<fillBlocks, 256>>>(ei, E);
    // layer-1 aggregation (per-edge dinv)
    k_agg_csr<false><<<aggBlocks, 256>>>(h, b1, a, n);
    // layer-2 GEMM (epilogue scales rows by dinv) + pure gather-add agg
    k_gemm2<<<gemmBlocks, 256, SM_BYTES>>>(a, wh2, wl2, h, n);
    k_agg_csr<true><<<aggBlocks, 256>>>(h, b2, out, n);
}